// round 14
// baseline (speedup 1.0000x reference)
#include <cuda_runtime.h>
#include <cuda_fp16.h>
#include <cstdint>

#define NN 8192
#define DD 256
#define BM 64
#define BN 32

// ---------------- device global scratch ----------------
__device__ __half g_Qhi[NN * DD], g_Qlo[NN * DD];
__device__ __half g_Khi[NN * DD], g_Klo[NN * DD];
__device__ __half g_V[NN * DD];
__device__ __half g_Xhi[NN * DD], g_Xlo[NN * DD];
__device__ __half g_Whi[3 * DD * DD], g_Wlo[3 * DD * DD];  // [z][col][k]
__device__ uint32_t g_mask[NN * (NN / 32)];
__device__ float g_Op[2][NN * DD];      // per-group fp32 O master
__device__ float g_m2[2][NN], g_l2[2][NN];

// ---------------- helpers ----------------
__device__ __forceinline__ uint32_t smem_u32(const void* p) {
    uint32_t a;
    asm("{ .reg .u64 t; cvta.to.shared.u64 t, %1; cvt.u32.u64 %0, t; }" : "=r"(a) : "l"(p));
    return a;
}
__device__ __forceinline__ uint32_t swz(int r, int c) {
    return (uint32_t)(r * 512 + ((((c ^ r) & 7) | (c & 24)) << 4));
}
__device__ __forceinline__ void ldm_x4(uint32_t a, uint32_t* r) {
    asm volatile("ldmatrix.sync.aligned.m8n8.x4.shared.b16 {%0,%1,%2,%3}, [%4];"
                 : "=r"(r[0]), "=r"(r[1]), "=r"(r[2]), "=r"(r[3]) : "r"(a));
}
__device__ __forceinline__ void ldm_x4t(uint32_t a, uint32_t* r) {
    asm volatile("ldmatrix.sync.aligned.m8n8.x4.trans.shared.b16 {%0,%1,%2,%3}, [%4];"
                 : "=r"(r[0]), "=r"(r[1]), "=r"(r[2]), "=r"(r[3]) : "r"(a));
}
__device__ __forceinline__ void mma_f16(float* c, const uint32_t* a, const uint32_t* b) {
    asm volatile(
        "mma.sync.aligned.m16n8k16.row.col.f32.f16.f16.f32 "
        "{%0,%1,%2,%3},{%4,%5,%6,%7},{%8,%9},{%0,%1,%2,%3};"
        : "+f"(c[0]), "+f"(c[1]), "+f"(c[2]), "+f"(c[3])
        : "r"(a[0]), "r"(a[1]), "r"(a[2]), "r"(a[3]), "r"(b[0]), "r"(b[1]));
}
// fp16-accumulate variant (D,C fp16) for the PV product
__device__ __forceinline__ void mma_f16acc(uint32_t* c, const uint32_t* a, const uint32_t* b) {
    asm volatile(
        "mma.sync.aligned.m16n8k16.row.col.f16.f16.f16.f16 "
        "{%0,%1},{%2,%3,%4,%5},{%6,%7},{%0,%1};"
        : "+r"(c[0]), "+r"(c[1])
        : "r"(a[0]), "r"(a[1]), "r"(a[2]), "r"(a[3]), "r"(b[0]), "r"(b[1]));
}
__device__ __forceinline__ void cpa16(uint32_t dst, const void* src) {
    asm volatile("cp.async.cg.shared.global [%0], [%1], 16;" :: "r"(dst), "l"(src));
}
#define CPA_COMMIT() asm volatile("cp.async.commit_group;")
#define CPA_WAIT0() asm volatile("cp.async.wait_group 0;")
#define CPA_WAIT1() asm volatile("cp.async.wait_group 1;")
#define GBAR(id) asm volatile("bar.sync %0, 128;" :: "r"(id) : "memory")

template <int R, int NT>
__device__ __forceinline__ void cpa_tile(uint32_t sbase, const __half* g,
                                         int row0, int ltid) {
    const char* gp = (const char*)(g + (size_t)row0 * DD);
    #pragma unroll
    for (int t = 0; t < (R * 32) / NT; ++t) {
        int idx = ltid + t * NT;
        int r = idx >> 5, c = idx & 31;
        cpa16(sbase + swz(r, c), gp + r * 512 + c * 16);
    }
}

// ---------------------------------------------------------------------------
// Pack adjacency to bitmask (int4 loads). grid=NN, block=256.
// ---------------------------------------------------------------------------
__global__ __launch_bounds__(256)
void pack_mask_kernel(const int* __restrict__ A) {
    const int row = blockIdx.x;
    const int lane = threadIdx.x & 31, w = threadIdx.x >> 5;
    const int4* arow = (const int4*)(A + (size_t)row * NN);
    #pragma unroll
    for (int it = 0; it < 8; ++it) {
        int blk = w + it * 8;
        int col0 = blk * 128 + lane * 4;
        int4 v = arow[blk * 32 + lane];
        uint32_t nib = (v.x != 0 ? 1u : 0u) | (v.y != 0 ? 2u : 0u) |
                       (v.z != 0 ? 4u : 0u) | (v.w != 0 ? 8u : 0u);
        uint32_t d = (uint32_t)(row - col0);
        if (d < 4u) nib |= 1u << d;
        uint32_t bits = nib << (4 * (lane & 7));
        bits |= __shfl_xor_sync(0xffffffffu, bits, 1);
        bits |= __shfl_xor_sync(0xffffffffu, bits, 2);
        bits |= __shfl_xor_sync(0xffffffffu, bits, 4);
        if ((lane & 7) == 0)
            g_mask[(size_t)row * (NN / 32) + blk * 4 + (lane >> 3)] = bits;
    }
}

// ---------------------------------------------------------------------------
// Split X -> fp16 hi/lo; W -> fp16 hi/lo transposed to [col][k].
// ---------------------------------------------------------------------------
__global__ __launch_bounds__(256)
void split_kernel(const float* __restrict__ X, const float* __restrict__ Wq,
                  const float* __restrict__ Wk, const float* __restrict__ Wv) {
    const int b = blockIdx.x, tid = threadIdx.x;
    if (b < 2048) {
        int i = b * 256 + tid;
        float4 v = reinterpret_cast<const float4*>(X)[i];
        __half2 h0 = __floats2half2_rn(v.x, v.y);
        __half2 h1 = __floats2half2_rn(v.z, v.w);
        float2 f0 = __half22float2(h0), f1 = __half22float2(h1);
        __half2 l0 = __floats2half2_rn(v.x - f0.x, v.y - f0.y);
        __half2 l1 = __floats2half2_rn(v.z - f1.x, v.w - f1.y);
        reinterpret_cast<__half2*>(g_Xhi)[2 * i] = h0;
        reinterpret_cast<__half2*>(g_Xhi)[2 * i + 1] = h1;
        reinterpret_cast<__half2*>(g_Xlo)[2 * i] = l0;
        reinterpret_cast<__half2*>(g_Xlo)[2 * i + 1] = l1;
    } else {
        int j = (b - 2048) * 256 + tid;
        int z = j >> 16, e = j & 65535;
        int k = e >> 8, col = e & 255;
        const float* W = (z == 0) ? Wq : (z == 1) ? Wk : Wv;
        float v = W[k * DD + col];
        __half h = __float2half_rn(v);
        g_Whi[z * DD * DD + col * DD + k] = h;
        g_Wlo[z * DD * DD + col * DD + k] = __float2half_rn(v - __half2float(h));
    }
}

// ---------------------------------------------------------------------------
// QKV projection on tensor cores (fp16 x3 products).
// ---------------------------------------------------------------------------
__global__ __launch_bounds__(256, 1)
void qkv_mma_kernel() {
    extern __shared__ char smem[];
    const int tid = threadIdx.x, warp = tid >> 5, lane = tid & 31;
    const int roww = warp & 3, colw = warp >> 2;
    const int g = lane >> 2, t4 = lane & 3;
    const int rowbase = blockIdx.x * 64, colbase = blockIdx.y * 128;
    const int z = blockIdx.z;

    const uint32_t sbase = smem_u32(smem);
    const uint32_t XH = sbase, XL = sbase + 32768;
    const uint32_t WH = sbase + 65536, WL = sbase + 131072;

    cpa_tile<64, 256>(XH, g_Xhi, rowbase, tid);
    cpa_tile<64, 256>(XL, g_Xlo, rowbase, tid);
    cpa_tile<128, 256>(WH, g_Whi + (size_t)z * DD * DD + (size_t)colbase * DD, 0, tid);
    cpa_tile<128, 256>(WL, g_Wlo + (size_t)z * DD * DD + (size_t)colbase * DD, 0, tid);
    CPA_COMMIT();
    CPA_WAIT0();
    __syncthreads();

    float C[8][4];
    #pragma unroll
    for (int nt = 0; nt < 8; ++nt) {
        C[nt][0] = 0.f; C[nt][1] = 0.f; C[nt][2] = 0.f; C[nt][3] = 0.f;
    }

    const int qr = 16 * roww + (lane & 15);
    const int qcsel = lane >> 4;
    const int bj_half = lane >> 4;
    const int bkcsel = (lane >> 3) & 1;
    const int br8 = lane & 7;

    #pragma unroll 4
    for (int kk = 0; kk < 16; ++kk) {
        uint32_t aH[4], aL[4];
        ldm_x4(XH + swz(qr, 2 * kk + qcsel), aH);
        ldm_x4(XL + swz(qr, 2 * kk + qcsel), aL);
        #pragma unroll
        for (int jjp = 0; jjp < 4; ++jjp) {
            int colrow = 64 * colw + 8 * (2 * jjp + bj_half) + br8;
            int kc = 2 * kk + bkcsel;
            uint32_t bH[4], bL[4];
            ldm_x4(WH + swz(colrow, kc), bH);
            ldm_x4(WL + swz(colrow, kc), bL);
            mma_f16(C[2 * jjp], aH, bH);
            mma_f16(C[2 * jjp], aL, bH);
            mma_f16(C[2 * jjp], aH, bL);
            mma_f16(C[2 * jjp + 1], aH, bH + 2);
            mma_f16(C[2 * jjp + 1], aL, bH + 2);
            mma_f16(C[2 * jjp + 1], aH, bL + 2);
        }
    }

    const int r0 = rowbase + 16 * roww + g, r1 = r0 + 8;
    #pragma unroll
    for (int nt = 0; nt < 8; ++nt) {
        int col = colbase + 64 * colw + 8 * nt + 2 * t4;
        if (z == 2) {
            *reinterpret_cast<__half2*>(&g_V[(size_t)r0 * DD + col]) =
                __floats2half2_rn(C[nt][0], C[nt][1]);
            *reinterpret_cast<__half2*>(&g_V[(size_t)r1 * DD + col]) =
                __floats2half2_rn(C[nt][2], C[nt][3]);
        } else {
            __half* Oh = (z == 0) ? g_Qhi : g_Khi;
            __half* Ol = (z == 0) ? g_Qlo : g_Klo;
            __half2 h0 = __floats2half2_rn(C[nt][0], C[nt][1]);
            float2 f0 = __half22float2(h0);
            __half2 l0 = __floats2half2_rn(C[nt][0] - f0.x, C[nt][1] - f0.y);
            __half2 h1 = __floats2half2_rn(C[nt][2], C[nt][3]);
            float2 f1 = __half22float2(h1);
            __half2 l1 = __floats2half2_rn(C[nt][2] - f1.x, C[nt][3] - f1.y);
            *reinterpret_cast<__half2*>(&Oh[(size_t)r0 * DD + col]) = h0;
            *reinterpret_cast<__half2*>(&Ol[(size_t)r0 * DD + col]) = l0;
            *reinterpret_cast<__half2*>(&Oh[(size_t)r1 * DD + col]) = h1;
            *reinterpret_cast<__half2*>(&Ol[(size_t)r1 * DD + col]) = l1;
        }
    }
}

// ---------------------------------------------------------------------------
// Flash attention: fp16 mma.sync, 2 free-running 4-warp groups (key-split).
// S: 3 products with double-buffered fragments. PV: fp16-accumulated, folded
// into an fp32 master in global memory every 4 key blocks.
// smem: Q hi/lo 64K | group0 {Khi,Klo,V} 48K | group1 48K = 160K
// ---------------------------------------------------------------------------
__global__ __launch_bounds__(256, 1)
void attn_kernel() {
    extern __shared__ char smem[];
    const int tid = threadIdx.x, warp = tid >> 5, lane = tid & 31;
    const int grp = warp >> 2, wg = warp & 3, ltid = tid & 127;
    const int g = lane >> 2, t4 = lane & 3;
    const int rowbase = blockIdx.x * BM;

    const uint32_t sbase = smem_u32(smem);
    const uint32_t sQH = sbase, sQL = sbase + 32768;
    const uint32_t KB = sbase + 65536 + grp * 49152;
    const uint32_t KH = KB, KL = KB + 16384, VS = KB + 32768;
    const int barid = grp + 1;

    cpa_tile<BM, 256>(sQH, g_Qhi, rowbase, tid);
    cpa_tile<BM, 256>(sQL, g_Qlo, rowbase, tid);
    cpa_tile<BN, 128>(KH, g_Khi, grp * BN, ltid);
    cpa_tile<BN, 128>(KL, g_Klo, grp * BN, ltid);
    CPA_COMMIT();

    uint32_t Ob[32][2];                     // fp16x2 block accumulators
    #pragma unroll
    for (int dt = 0; dt < 32; ++dt) { Ob[dt][0] = 0u; Ob[dt][1] = 0u; }
    float m0 = -1e30f, m1 = -1e30f, l0 = 0.f, l1 = 0.f;
    float m_lf0 = -1e30f, m_lf1 = -1e30f;   // master frame

    const int rg0 = rowbase + 16 * wg + g;
    const int rg1 = rg0 + 8;
    const uint32_t* mrow0 = g_mask + (size_t)rg0 * (NN / 32);
    const uint32_t* mrow1 = g_mask + (size_t)rg1 * (NN / 32);
    float* OpG = g_Op[grp];

    const int qr = 16 * wg + (lane & 15);
    const int qcsel = lane >> 4;
    const int k_j_half = lane >> 4;
    const int k_kcsel = (lane >> 3) & 1;
    const int kr8 = lane & 7;
    const int v_dtsel = lane >> 4;
    const int vlane = lane & 15;

    const int NITER = (NN / BN) / 2;   // 64
    for (int i = 0; i < NITER; ++i) {
        const int b = 2 * i + grp;

        cpa_tile<BN, 128>(VS, g_V, b * BN, ltid);
        CPA_COMMIT();
        CPA_WAIT1();               // K[b] (and Q) landed
        GBAR(barid);

        // ---- S = Q K^T, fp16 x3, double-buffered fragments ----
        uint32_t aH[2][4], aL[2][4], bH[2][4], bL[2][4];
        ldm_x4(sQH + swz(qr, qcsel), aH[0]);
        ldm_x4(sQL + swz(qr, qcsel), aL[0]);
        {
            int krow = 8 * k_j_half + kr8;
            ldm_x4(KH + swz(krow, k_kcsel), bH[0]);
            ldm_x4(KL + swz(krow, k_kcsel), bL[0]);
        }
        float S[4][4] = {};
        #pragma unroll
        for (int t = 0; t < 32; ++t) {
            const int kk = t >> 1, jjp = t & 1, cb = t & 1, ab = kk & 1;
            if (t + 1 < 32) {
                int nk = (t + 1) >> 1, nj = (t + 1) & 1;
                int krow = 8 * (2 * nj + k_j_half) + kr8;
                ldm_x4(KH + swz(krow, 2 * nk + k_kcsel), bH[cb ^ 1]);
                ldm_x4(KL + swz(krow, 2 * nk + k_kcsel), bL[cb ^ 1]);
            }
            if (jjp == 1 && kk + 1 < 16) {
                ldm_x4(sQH + swz(qr, 2 * (kk + 1) + qcsel), aH[ab ^ 1]);
                ldm_x4(sQL + swz(qr, 2 * (kk + 1) + qcsel), aL[ab ^ 1]);
            }
            float* S0 = S[2 * jjp];
            float* S1 = S[2 * jjp + 1];
            mma_f16(S0, aH[ab], bH[cb]);
            mma_f16(S1, aH[ab], bH[cb] + 2);
            mma_f16(S0, aL[ab], bH[cb]);
            mma_f16(S1, aL[ab], bH[cb] + 2);
            mma_f16(S0, aH[ab], bL[cb]);
            mma_f16(S1, aH[ab], bL[cb] + 2);
        }
        GBAR(barid);               // group done reading K[b]

        if (i + 1 < NITER) {
            cpa_tile<BN, 128>(KH, g_Khi, (b + 2) * BN, ltid);
            cpa_tile<BN, 128>(KL, g_Klo, (b + 2) * BN, ltid);
            CPA_COMMIT();
            CPA_WAIT1();           // V[b] landed (K still in flight)
        } else {
            CPA_WAIT0();
        }

        // ---- mask in place + row max ----
        const uint32_t mw0 = mrow0[b], mw1 = mrow1[b];
        float mt0 = -1e30f, mt1 = -1e30f;
        #pragma unroll
        for (int j = 0; j < 4; ++j)
            #pragma unroll
            for (int e = 0; e < 2; ++e) {
                int bit = 8 * j + 2 * t4 + e;
                S[j][e]     = ((mw0 >> bit) & 1u) ? S[j][e]     : -1e30f;
                S[j][2 + e] = ((mw1 >> bit) & 1u) ? S[j][2 + e] : -1e30f;
                mt0 = fmaxf(mt0, S[j][e]); mt1 = fmaxf(mt1, S[j][2 + e]);
            }
        mt0 = fmaxf(mt0, __shfl_xor_sync(0xffffffffu, mt0, 1));
        mt0 = fmaxf(mt0, __shfl_xor_sync(0xffffffffu, mt0, 2));
        mt1 = fmaxf(mt1, __shfl_xor_sync(0xffffffffu, mt1, 1));
        mt1 = fmaxf(mt1, __shfl_xor_sync(0xffffffffu, mt1, 2));

        const float mn0 = fmaxf(m0, mt0), mn1 = fmaxf(m1, mt1);
        const float sc0 = __expf(m0 - mn0), sc1 = __expf(m1 - mn1);

        // ---- exp -> fp16 P frags; l sums the rounded p ----
        uint32_t Ph[4][2];
        float rs0 = 0.f, rs1 = 0.f;
        #pragma unroll
        for (int j = 0; j < 4; ++j) {
            float p0 = __expf(S[j][0] - mn0), p1 = __expf(S[j][1] - mn0);
            float p2 = __expf(S[j][2] - mn1), p3 = __expf(S[j][3] - mn1);
            __half2 h01 = __floats2half2_rn(p0, p1);
            __half2 h23 = __floats2half2_rn(p2, p3);
            Ph[j][0] = *reinterpret_cast<uint32_t*>(&h01);
            Ph[j][1] = *reinterpret_cast<uint32_t*>(&h23);
            float2 f01 = __half22float2(h01), f23 = __half22float2(h23);
            rs0 += f01.x + f01.y;
            rs1 += f23.x + f23.y;
        }
        rs0 += __shfl_xor_sync(0xffffffffu, rs0, 1);
        rs0 += __shfl_xor_sync(0xffffffffu, rs0, 2);
        rs1 += __shfl_xor_sync(0xffffffffu, rs1, 1);
        rs1 += __shfl_xor_sync(0xffffffffu, rs1, 2);
        l0 = l0 * sc0 + rs0;
        l1 = l1 * sc1 + rs1;
        m0 = mn0; m1 = mn1;

        // rescale fp16 block accumulator (half2 multiplies)
        if (__ballot_sync(0xffffffffu, (sc0 != 1.f) || (sc1 != 1.f))) {
            __half2 s0 = __float2half2_rn(sc0), s1 = __float2half2_rn(sc1);
            #pragma unroll
            for (int dt = 0; dt < 32; ++dt) {
                __half2 v0 = *reinterpret_cast<__half2*>(&Ob[dt][0]);
                __half2 v1 = *reinterpret_cast<__half2*>(&Ob[dt][1]);
                v0 = __hmul2(v0, s0); v1 = __hmul2(v1, s1);
                Ob[dt][0] = *reinterpret_cast<uint32_t*>(&v0);
                Ob[dt][1] = *reinterpret_cast<uint32_t*>(&v1);
            }
        }

        GBAR(barid);               // V[b] visible to whole group

        // ---- Ob += P V (fp16 accum, prefetched V frags) ----
        #pragma unroll
        for (int kp = 0; kp < 2; ++kp) {
            uint32_t aP[4] = {Ph[2 * kp][0], Ph[2 * kp][1], Ph[2 * kp + 1][0], Ph[2 * kp + 1][1]};
            const int vr = 16 * kp + vlane;
            uint32_t bV[2][4];
            ldm_x4t(VS + swz(vr, v_dtsel), bV[0]);
            #pragma unroll
            for (int dtp = 0; dtp < 16; ++dtp) {
                if (dtp + 1 < 16)
                    ldm_x4t(VS + swz(vr, 2 * (dtp + 1) + v_dtsel), bV[(dtp & 1) ^ 1]);
                mma_f16acc(Ob[2 * dtp], aP, bV[dtp & 1]);
                mma_f16acc(Ob[2 * dtp + 1], aP, bV[dtp & 1] + 2);
            }
        }
        GBAR(barid);               // group done reading V[b]

        // ---- fold fp16 block into fp32 global master every 4 blocks ----
        if ((i & 3) == 3) {
            float2* p0 = reinterpret_cast<float2*>(OpG + (size_t)rg0 * DD);
            float2* p1 = reinterpret_cast<float2*>(OpG + (size_t)rg1 * DD);
            if (i == 3) {
                #pragma unroll
                for (int dt = 0; dt < 32; ++dt) {
                    p0[4 * dt + t4] = __half22float2(*reinterpret_cast<__half2*>(&Ob[dt][0]));
                    p1[4 * dt + t4] = __half22float2(*reinterpret_cast<__half2*>(&Ob[dt][1]));
                }
            } else {
                const float f0 = __expf(m_lf0 - m0), f1 = __expf(m_lf1 - m1);
                #pragma unroll
                for (int dt = 0; dt < 32; ++dt) {
                    float2 a0 = p0[4 * dt + t4];
                    float2 a1 = p1[4 * dt + t4];
                    float2 b0 = __half22float2(*reinterpret_cast<__half2*>(&Ob[dt][0]));
                    float2 b1 = __half22float2(*reinterpret_cast<__half2*>(&Ob[dt][1]));
                    p0[4 * dt + t4] = make_float2(a0.x * f0 + b0.x, a0.y * f0 + b0.y);
                    p1[4 * dt + t4] = make_float2(a1.x * f1 + b1.x, a1.y * f1 + b1.y);
                }
            }
            #pragma unroll
            for (int dt = 0; dt < 32; ++dt) { Ob[dt][0] = 0u; Ob[dt][1] = 0u; }
            m_lf0 = m0; m_lf1 = m1;
        }
    }

    // final fold happened at i=63; store m,l (master frame == current m)
    if (t4 == 0) {
        g_m2[grp][rg0] = m0; g_m2[grp][rg1] = m1;
        g_l2[grp][rg0] = l0; g_l2[grp][rg1] = l1;
    }
}

// ---------------------------------------------------------------------------
// Combine the two key-split halves: Out = (Op0*w0 + Op1*w1) / (l0*w0 + l1*w1)
// ---------------------------------------------------------------------------
__global__ __launch_bounds__(256)
void combine_kernel(float* __restrict__ Out) {
    int idx = blockIdx.x * 256 + threadIdx.x;
    int row = idx >> 8;
    float m0 = g_m2[0][row], m1 = g_m2[1][row];
    float mm = fmaxf(m0, m1);
    float w0 = __expf(m0 - mm), w1 = __expf(m1 - mm);
    float denom = g_l2[0][row] * w0 + g_l2[1][row] * w1;
    Out[idx] = (g_Op[0][idx] * w0 + g_Op[1][idx] * w1) / denom;
}

// ---------------------------------------------------------------------------
extern "C" void kernel_launch(void* const* d_in, const int* in_sizes, int n_in,
                              void* d_out, int out_size) {
    const float* X  = (const float*)d_in[0];
    const int*   A  = (const int*)d_in[1];
    const float* Wq = (const float*)d_in[2];
    const float* Wk = (const float*)d_in[3];
    const float* Wv = (const float*)d_in[4];
    float* Out = (float*)d_out;

    static int attr_set = 0;
    const int smem_attn = 163840;
    const int smem_qkv = 196608;
    if (!attr_set) {
        cudaFuncSetAttribute(attn_kernel, cudaFuncAttributeMaxDynamicSharedMemorySize,
                             smem_attn);
        cudaFuncSetAttribute(qkv_mma_kernel, cudaFuncAttributeMaxDynamicSharedMemorySize,
                             smem_qkv);
        attr_set = 1;
    }

    pack_mask_kernel<<<NN, 256>>>(A);
    split_kernel<<<2048 + 768, 256>>>(X, Wq, Wk, Wv);
    qkv_mma_kernel<<<dim3(NN / 64, 2, 3), 256, smem_qkv>>>();
    attn_kernel<<<NN / BM, 256, smem_attn>>>();
    combine_kernel<<<NN * DD / 256, 256>>>(Out);
}

// round 15
// speedup vs baseline: 1.5028x; 1.5028x over previous
#include <cuda_runtime.h>
#include <cuda_fp16.h>
#include <cstdint>

#define NN 8192
#define DD 256
#define BM 64
#define BN 32

// ---------------- device global scratch ----------------
__device__ __half g_Qhi[NN * DD], g_Qlo[NN * DD];
__device__ __half g_Khi[NN * DD], g_Klo[NN * DD];
__device__ __half g_V[NN * DD];                       // single fp16
__device__ __half g_Xhi[NN * DD], g_Xlo[NN * DD];
__device__ __half g_Whi[3 * DD * DD], g_Wlo[3 * DD * DD];  // [z][col][k] (transposed)
__device__ uint32_t g_mask[NN * (NN / 32)];

// ---------------- helpers ----------------
__device__ __forceinline__ uint32_t smem_u32(const void* p) {
    uint32_t a;
    asm("{ .reg .u64 t; cvta.to.shared.u64 t, %1; cvt.u32.u64 %0, t; }" : "=r"(a) : "l"(p));
    return a;
}
// 16B-chunk XOR swizzle within 128B window; rows are 512B (256 fp16)
__device__ __forceinline__ uint32_t swz(int r, int c) {
    return (uint32_t)(r * 512 + ((((c ^ r) & 7) | (c & 24)) << 4));
}
__device__ __forceinline__ void ldm_x4(uint32_t a, uint32_t* r) {
    asm volatile("ldmatrix.sync.aligned.m8n8.x4.shared.b16 {%0,%1,%2,%3}, [%4];"
                 : "=r"(r[0]), "=r"(r[1]), "=r"(r[2]), "=r"(r[3]) : "r"(a));
}
__device__ __forceinline__ void ldm_x4t(uint32_t a, uint32_t* r) {
    asm volatile("ldmatrix.sync.aligned.m8n8.x4.trans.shared.b16 {%0,%1,%2,%3}, [%4];"
                 : "=r"(r[0]), "=r"(r[1]), "=r"(r[2]), "=r"(r[3]) : "r"(a));
}
__device__ __forceinline__ void mma_f16(float* c, const uint32_t* a, const uint32_t* b) {
    asm volatile(
        "mma.sync.aligned.m16n8k16.row.col.f32.f16.f16.f32 "
        "{%0,%1,%2,%3},{%4,%5,%6,%7},{%8,%9},{%0,%1,%2,%3};"
        : "+f"(c[0]), "+f"(c[1]), "+f"(c[2]), "+f"(c[3])
        : "r"(a[0]), "r"(a[1]), "r"(a[2]), "r"(a[3]), "r"(b[0]), "r"(b[1]));
}
// fp16-accumulate variant (D,C fp16) — used ONLY for the small S corrections
__device__ __forceinline__ void mma_f16acc(uint32_t* c, const uint32_t* a, const uint32_t* b) {
    asm volatile(
        "mma.sync.aligned.m16n8k16.row.col.f16.f16.f16.f16 "
        "{%0,%1},{%2,%3,%4,%5},{%6,%7},{%0,%1};"
        : "+r"(c[0]), "+r"(c[1])
        : "r"(a[0]), "r"(a[1]), "r"(a[2]), "r"(a[3]), "r"(b[0]), "r"(b[1]));
}
__device__ __forceinline__ void cpa16(uint32_t dst, const void* src) {
    asm volatile("cp.async.cg.shared.global [%0], [%1], 16;" :: "r"(dst), "l"(src));
}
#define CPA_COMMIT() asm volatile("cp.async.commit_group;")
#define CPA_WAIT0() asm volatile("cp.async.wait_group 0;")
#define CPA_WAIT1() asm volatile("cp.async.wait_group 1;")
#define GBAR(id) asm volatile("bar.sync %0, 128;" :: "r"(id) : "memory")

// tile loader: R rows x 256 fp16 (512B rows), NT participating threads
template <int R, int NT>
__device__ __forceinline__ void cpa_tile(uint32_t sbase, const __half* g,
                                         int row0, int ltid) {
    const char* gp = (const char*)(g + (size_t)row0 * DD);
    #pragma unroll
    for (int t = 0; t < (R * 32) / NT; ++t) {
        int idx = ltid + t * NT;
        int r = idx >> 5, c = idx & 31;
        cpa16(sbase + swz(r, c), gp + r * 512 + c * 16);
    }
}

// ---------------------------------------------------------------------------
// Pack adjacency to bitmask (int4 loads). grid=NN, block=256.
// ---------------------------------------------------------------------------
__global__ __launch_bounds__(256)
void pack_mask_kernel(const int* __restrict__ A) {
    const int row = blockIdx.x;
    const int lane = threadIdx.x & 31, w = threadIdx.x >> 5;
    const int4* arow = (const int4*)(A + (size_t)row * NN);
    #pragma unroll
    for (int it = 0; it < 8; ++it) {
        int blk = w + it * 8;
        int col0 = blk * 128 + lane * 4;
        int4 v = arow[blk * 32 + lane];
        uint32_t nib = (v.x != 0 ? 1u : 0u) | (v.y != 0 ? 2u : 0u) |
                       (v.z != 0 ? 4u : 0u) | (v.w != 0 ? 8u : 0u);
        uint32_t d = (uint32_t)(row - col0);
        if (d < 4u) nib |= 1u << d;
        uint32_t bits = nib << (4 * (lane & 7));
        bits |= __shfl_xor_sync(0xffffffffu, bits, 1);
        bits |= __shfl_xor_sync(0xffffffffu, bits, 2);
        bits |= __shfl_xor_sync(0xffffffffu, bits, 4);
        if ((lane & 7) == 0)
            g_mask[(size_t)row * (NN / 32) + blk * 4 + (lane >> 3)] = bits;
    }
}

// ---------------------------------------------------------------------------
// Split X -> fp16 hi/lo; W -> fp16 hi/lo TRANSPOSED to [col][k].
// ---------------------------------------------------------------------------
__global__ __launch_bounds__(256)
void split_kernel(const float* __restrict__ X, const float* __restrict__ Wq,
                  const float* __restrict__ Wk, const float* __restrict__ Wv) {
    const int b = blockIdx.x, tid = threadIdx.x;
    if (b < 2048) {
        int i = b * 256 + tid;   // float4 index over X
        float4 v = reinterpret_cast<const float4*>(X)[i];
        __half2 h0 = __floats2half2_rn(v.x, v.y);
        __half2 h1 = __floats2half2_rn(v.z, v.w);
        float2 f0 = __half22float2(h0), f1 = __half22float2(h1);
        __half2 l0 = __floats2half2_rn(v.x - f0.x, v.y - f0.y);
        __half2 l1 = __floats2half2_rn(v.z - f1.x, v.w - f1.y);
        reinterpret_cast<__half2*>(g_Xhi)[2 * i] = h0;
        reinterpret_cast<__half2*>(g_Xhi)[2 * i + 1] = h1;
        reinterpret_cast<__half2*>(g_Xlo)[2 * i] = l0;
        reinterpret_cast<__half2*>(g_Xlo)[2 * i + 1] = l1;
    } else {
        int j = (b - 2048) * 256 + tid;          // elem over 3*65536
        int z = j >> 16, e = j & 65535;
        int k = e >> 8, col = e & 255;
        const float* W = (z == 0) ? Wq : (z == 1) ? Wk : Wv;
        float v = W[k * DD + col];
        __half h = __float2half_rn(v);
        g_Whi[z * DD * DD + col * DD + k] = h;
        g_Wlo[z * DD * DD + col * DD + k] = __float2half_rn(v - __half2float(h));
    }
}

// ---------------------------------------------------------------------------
// QKV projection on tensor cores (fp16 x3 products).
// grid (NN/64, 2, 3), block 256 (8 warps: 4 row-split x 2 col-split of 64).
// smem: Xhi 32K | Xlo 32K | Whi 64K | Wlo 64K = 192K
// ---------------------------------------------------------------------------
__global__ __launch_bounds__(256, 1)
void qkv_mma_kernel() {
    extern __shared__ char smem[];
    const int tid = threadIdx.x, warp = tid >> 5, lane = tid & 31;
    const int roww = warp & 3, colw = warp >> 2;
    const int g = lane >> 2, t4 = lane & 3;
    const int rowbase = blockIdx.x * 64, colbase = blockIdx.y * 128;
    const int z = blockIdx.z;

    const uint32_t sbase = smem_u32(smem);
    const uint32_t XH = sbase, XL = sbase + 32768;
    const uint32_t WH = sbase + 65536, WL = sbase + 131072;

    cpa_tile<64, 256>(XH, g_Xhi, rowbase, tid);
    cpa_tile<64, 256>(XL, g_Xlo, rowbase, tid);
    cpa_tile<128, 256>(WH, g_Whi + (size_t)z * DD * DD + (size_t)colbase * DD, 0, tid);
    cpa_tile<128, 256>(WL, g_Wlo + (size_t)z * DD * DD + (size_t)colbase * DD, 0, tid);
    CPA_COMMIT();
    CPA_WAIT0();
    __syncthreads();

    float C[8][4];
    #pragma unroll
    for (int nt = 0; nt < 8; ++nt) {
        C[nt][0] = 0.f; C[nt][1] = 0.f; C[nt][2] = 0.f; C[nt][3] = 0.f;
    }

    const int qr = 16 * roww + (lane & 15);
    const int qcsel = lane >> 4;
    const int bj_half = lane >> 4;
    const int bkcsel = (lane >> 3) & 1;
    const int br8 = lane & 7;

    #pragma unroll 4
    for (int kk = 0; kk < 16; ++kk) {
        uint32_t aH[4], aL[4];
        ldm_x4(XH + swz(qr, 2 * kk + qcsel), aH);
        ldm_x4(XL + swz(qr, 2 * kk + qcsel), aL);
        #pragma unroll
        for (int jjp = 0; jjp < 4; ++jjp) {
            int colrow = 64 * colw + 8 * (2 * jjp + bj_half) + br8;
            int kc = 2 * kk + bkcsel;
            uint32_t bH[4], bL[4];
            ldm_x4(WH + swz(colrow, kc), bH);
            ldm_x4(WL + swz(colrow, kc), bL);
            mma_f16(C[2 * jjp], aH, bH);
            mma_f16(C[2 * jjp], aL, bH);
            mma_f16(C[2 * jjp], aH, bL);
            mma_f16(C[2 * jjp + 1], aH, bH + 2);
            mma_f16(C[2 * jjp + 1], aL, bH + 2);
            mma_f16(C[2 * jjp + 1], aH, bL + 2);
        }
    }

    // epilogue
    const int r0 = rowbase + 16 * roww + g, r1 = r0 + 8;
    #pragma unroll
    for (int nt = 0; nt < 8; ++nt) {
        int col = colbase + 64 * colw + 8 * nt + 2 * t4;
        if (z == 2) {
            *reinterpret_cast<__half2*>(&g_V[(size_t)r0 * DD + col]) =
                __floats2half2_rn(C[nt][0], C[nt][1]);
            *reinterpret_cast<__half2*>(&g_V[(size_t)r1 * DD + col]) =
                __floats2half2_rn(C[nt][2], C[nt][3]);
        } else {
            __half* Oh = (z == 0) ? g_Qhi : g_Khi;
            __half* Ol = (z == 0) ? g_Qlo : g_Klo;
            __half2 h0 = __floats2half2_rn(C[nt][0], C[nt][1]);
            float2 f0 = __half22float2(h0);
            __half2 l0 = __floats2half2_rn(C[nt][0] - f0.x, C[nt][1] - f0.y);
            __half2 h1 = __floats2half2_rn(C[nt][2], C[nt][3]);
            float2 f1 = __half22float2(h1);
            __half2 l1 = __floats2half2_rn(C[nt][2] - f1.x, C[nt][3] - f1.y);
            *reinterpret_cast<__half2*>(&Oh[(size_t)r0 * DD + col]) = h0;
            *reinterpret_cast<__half2*>(&Ol[(size_t)r0 * DD + col]) = l0;
            *reinterpret_cast<__half2*>(&Oh[(size_t)r1 * DD + col]) = h1;
            *reinterpret_cast<__half2*>(&Ol[(size_t)r1 * DD + col]) = l1;
        }
    }
}

// ---------------------------------------------------------------------------
// Flash attention, fp16 mma.sync, 8 warps in 2 free-running groups.
// S: hi-product in fp32-acc + 2 correction products in fp16-acc (folded at
// softmax). PV: 1 product, fp32 acc. l summed from rounded p.
// smem: Q hi/lo 64K | group0 {Khi,Klo,V} 48K | group1 48K = 160K
// ---------------------------------------------------------------------------
__global__ __launch_bounds__(256, 1)
void attn_kernel(float* __restrict__ Out) {
    extern __shared__ char smem[];
    const int tid = threadIdx.x, warp = tid >> 5, lane = tid & 31;
    const int grp = warp >> 2, wg = warp & 3, ltid = tid & 127;
    const int g = lane >> 2, t4 = lane & 3;
    const int rowbase = blockIdx.x * BM;

    const uint32_t sbase = smem_u32(smem);
    const uint32_t sQH = sbase, sQL = sbase + 32768;
    const uint32_t KB = sbase + 65536 + grp * 49152;
    const uint32_t KH = KB, KL = KB + 16384, VS = KB + 32768;
    const int barid = grp + 1;

    cpa_tile<BM, 256>(sQH, g_Qhi, rowbase, tid);
    cpa_tile<BM, 256>(sQL, g_Qlo, rowbase, tid);
    cpa_tile<BN, 128>(KH, g_Khi, grp * BN, ltid);
    cpa_tile<BN, 128>(KL, g_Klo, grp * BN, ltid);
    CPA_COMMIT();

    float O[32][4];
    #pragma unroll
    for (int dt = 0; dt < 32; ++dt) {
        O[dt][0] = 0.f; O[dt][1] = 0.f; O[dt][2] = 0.f; O[dt][3] = 0.f;
    }
    float m0 = -1e30f, m1 = -1e30f, l0 = 0.f, l1 = 0.f;

    const int rg0 = rowbase + 16 * wg + g;
    const int rg1 = rg0 + 8;
    const uint32_t* mrow0 = g_mask + (size_t)rg0 * (NN / 32);
    const uint32_t* mrow1 = g_mask + (size_t)rg1 * (NN / 32);

    const int qr = 16 * wg + (lane & 15);
    const int qcsel = lane >> 4;
    const int k_j_half = lane >> 4;
    const int k_kcsel = (lane >> 3) & 1;
    const int kr8 = lane & 7;
    const int v_dtsel = lane >> 4;
    const int vlane = lane & 15;

    const int NBLK = NN / BN;
    for (int i = 0; i < NBLK / 2; ++i) {
        const int b = 2 * i + grp;

        cpa_tile<BN, 128>(VS, g_V, b * BN, ltid);
        CPA_COMMIT();
        CPA_WAIT1();               // K[b] (and Q) landed
        GBAR(barid);

        // ---- S = Q K^T: hi product fp32-acc, corrections fp16-acc ----
        float S[4][4] = {};
        uint32_t Sc[4][2];
        #pragma unroll
        for (int j = 0; j < 4; ++j) { Sc[j][0] = 0u; Sc[j][1] = 0u; }
        #pragma unroll 4
        for (int kk = 0; kk < 16; ++kk) {
            uint32_t aH[4], aL[4];
            ldm_x4(sQH + swz(qr, 2 * kk + qcsel), aH);
            ldm_x4(sQL + swz(qr, 2 * kk + qcsel), aL);
            #pragma unroll
            for (int jjp = 0; jjp < 2; ++jjp) {
                int krow = 8 * (2 * jjp + k_j_half) + kr8;
                int kc = 2 * kk + k_kcsel;
                uint32_t bH[4], bL[4];
                ldm_x4(KH + swz(krow, kc), bH);
                ldm_x4(KL + swz(krow, kc), bL);
                mma_f16(S[2 * jjp], aH, bH);
                mma_f16(S[2 * jjp + 1], aH, bH + 2);
                mma_f16acc(Sc[2 * jjp], aL, bH);
                mma_f16acc(Sc[2 * jjp + 1], aL, bH + 2);
                mma_f16acc(Sc[2 * jjp], aH, bL);
                mma_f16acc(Sc[2 * jjp + 1], aH, bL + 2);
            }
        }
        GBAR(barid);               // group done reading K[b]

        if (i + 1 < NBLK / 2) {
            cpa_tile<BN, 128>(KH, g_Khi, (b + 2) * BN, ltid);
            cpa_tile<BN, 128>(KL, g_Klo, (b + 2) * BN, ltid);
            CPA_COMMIT();
            CPA_WAIT1();           // V[b] landed (K still in flight)
        } else {
            CPA_WAIT0();
        }

        // ---- fold corrections, mask in place + row max ----
        const uint32_t mw0 = mrow0[b], mw1 = mrow1[b];
        float mt0 = -1e30f, mt1 = -1e30f;
        #pragma unroll
        for (int j = 0; j < 4; ++j) {
            float2 cA = __half22float2(*reinterpret_cast<__half2*>(&Sc[j][0]));
            float2 cB = __half22float2(*reinterpret_cast<__half2*>(&Sc[j][1]));
            S[j][0] += cA.x; S[j][1] += cA.y;
            S[j][2] += cB.x; S[j][3] += cB.y;
            #pragma unroll
            for (int e = 0; e < 2; ++e) {
                int bit = 8 * j + 2 * t4 + e;
                S[j][e]     = ((mw0 >> bit) & 1u) ? S[j][e]     : -1e30f;
                S[j][2 + e] = ((mw1 >> bit) & 1u) ? S[j][2 + e] : -1e30f;
                mt0 = fmaxf(mt0, S[j][e]); mt1 = fmaxf(mt1, S[j][2 + e]);
            }
        }
        mt0 = fmaxf(mt0, __shfl_xor_sync(0xffffffffu, mt0, 1));
        mt0 = fmaxf(mt0, __shfl_xor_sync(0xffffffffu, mt0, 2));
        mt1 = fmaxf(mt1, __shfl_xor_sync(0xffffffffu, mt1, 1));
        mt1 = fmaxf(mt1, __shfl_xor_sync(0xffffffffu, mt1, 2));

        const float mn0 = fmaxf(m0, mt0), mn1 = fmaxf(m1, mt1);
        const float sc0 = __expf(m0 - mn0), sc1 = __expf(m1 - mn1);

        // ---- exp (masked lanes underflow to exact 0) -> fp16 P frags ----
        uint32_t Ph[4][2];
        float rs0 = 0.f, rs1 = 0.f;
        #pragma unroll
        for (int j = 0; j < 4; ++j) {
            float p0 = __expf(S[j][0] - mn0), p1 = __expf(S[j][1] - mn0);
            float p2 = __expf(S[j][2] - mn1), p3 = __expf(S[j][3] - mn1);
            __half2 h01 = __floats2half2_rn(p0, p1);
            __half2 h23 = __floats2half2_rn(p2, p3);
            Ph[j][0] = *reinterpret_cast<uint32_t*>(&h01);
            Ph[j][1] = *reinterpret_cast<uint32_t*>(&h23);
            float2 f01 = __half22float2(h01), f23 = __half22float2(h23);
            rs0 += f01.x + f01.y;   // sum the ROUNDED p (matches PV numerator)
            rs1 += f23.x + f23.y;
        }
        rs0 += __shfl_xor_sync(0xffffffffu, rs0, 1);
        rs0 += __shfl_xor_sync(0xffffffffu, rs0, 2);
        rs1 += __shfl_xor_sync(0xffffffffu, rs1, 1);
        rs1 += __shfl_xor_sync(0xffffffffu, rs1, 2);
        l0 = l0 * sc0 + rs0;
        l1 = l1 * sc1 + rs1;
        m0 = mn0; m1 = mn1;

        if (__ballot_sync(0xffffffffu, (sc0 != 1.f) || (sc1 != 1.f))) {
            #pragma unroll
            for (int dt = 0; dt < 32; ++dt) {
                O[dt][0] *= sc0; O[dt][1] *= sc0;
                O[dt][2] *= sc1; O[dt][3] *= sc1;
            }
        }

        GBAR(barid);               // V[b] visible to whole group

        // ---- O += P V (single product, fp32 acc, x4 trans) ----
        #pragma unroll
        for (int kp = 0; kp < 2; ++kp) {
            uint32_t aH[4] = {Ph[2 * kp][0], Ph[2 * kp][1], Ph[2 * kp + 1][0], Ph[2 * kp + 1][1]};
            const int vr = 16 * kp + vlane;
            #pragma unroll
            for (int dtp = 0; dtp < 16; ++dtp) {
                uint32_t bV[4];
                ldm_x4t(VS + swz(vr, 2 * dtp + v_dtsel), bV);
                mma_f16(O[2 * dtp], aH, bV);
                mma_f16(O[2 * dtp + 1], aH, bV + 2);
            }
        }
        GBAR(barid);               // group done reading V[b]
    }

    // ---- merge groups ----
    __syncthreads();
    float* Os = reinterpret_cast<float*>(smem + 65536);   // [64][264] padded
    float* ml = reinterpret_cast<float*>(smem + 133120);  // m[64], l[64]
    const int r0l = 16 * wg + g, r1l = r0l + 8;
    if (grp == 1) {
        #pragma unroll
        for (int dt = 0; dt < 32; ++dt) {
            int c = 8 * dt + 2 * t4;
            Os[r0l * 264 + c] = O[dt][0]; Os[r0l * 264 + c + 1] = O[dt][1];
            Os[r1l * 264 + c] = O[dt][2]; Os[r1l * 264 + c + 1] = O[dt][3];
        }
        if (t4 == 0) {
            ml[r0l] = m0; ml[64 + r0l] = l0;
            ml[r1l] = m1; ml[64 + r1l] = l1;
        }
    }
    __syncthreads();
    if (grp == 0) {
        float mo0 = ml[r0l], lo0 = ml[64 + r0l];
        float mo1 = ml[r1l], lo1 = ml[64 + r1l];
        float mm0 = fmaxf(m0, mo0), mm1 = fmaxf(m1, mo1);
        float wa0 = __expf(m0 - mm0), wb0 = __expf(mo0 - mm0);
        float wa1 = __expf(m1 - mm1), wb1 = __expf(mo1 - mm1);
        float inv0 = 1.f / (l0 * wa0 + lo0 * wb0);
        float inv1 = 1.f / (l1 * wa1 + lo1 * wb1);
        float2* o0 = reinterpret_cast<float2*>(Out + (size_t)rg0 * DD);
        float2* o1 = reinterpret_cast<float2*>(Out + (size_t)rg1 * DD);
        #pragma unroll
        for (int dt = 0; dt < 32; ++dt) {
            int c = 8 * dt + 2 * t4;
            o0[4 * dt + t4] = make_float2(
                (O[dt][0] * wa0 + Os[r0l * 264 + c] * wb0) * inv0,
                (O[dt][1] * wa0 + Os[r0l * 264 + c + 1] * wb0) * inv0);
            o1[4 * dt + t4] = make_float2(
                (O[dt][2] * wa1 + Os[r1l * 264 + c] * wb1) * inv1,
                (O[dt][3] * wa1 + Os[r1l * 264 + c + 1] * wb1) * inv1);
        }
    }
}

// ---------------------------------------------------------------------------
extern "C" void kernel_launch(void* const* d_in, const int* in_sizes, int n_in,
                              void* d_out, int out_size) {
    const float* X  = (const float*)d_in[0];
    const int*   A  = (const int*)d_in[1];
    const float* Wq = (const float*)d_in[2];
    const float* Wk = (const float*)d_in[3];
    const float* Wv = (const float*)d_in[4];
    float* Out = (float*)d_out;

    static int attr_set = 0;
    const int smem_attn = 163840;
    const int smem_qkv = 196608;
    if (!attr_set) {
        cudaFuncSetAttribute(attn_kernel, cudaFuncAttributeMaxDynamicSharedMemorySize,
                             smem_attn);
        cudaFuncSetAttribute(qkv_mma_kernel, cudaFuncAttributeMaxDynamicSharedMemorySize,
                             smem_qkv);
        attr_set = 1;
    }

    pack_mask_kernel<<<NN, 256>>>(A);
    split_kernel<<<2048 + 768, 256>>>(X, Wq, Wk, Wv);
    qkv_mma_kernel<<<dim3(NN / 64, 2, 3), 256, smem_qkv>>>();
    attn_kernel<<<NN / BM, 256, smem_attn>>>(Out);
}